// round 3
// baseline (speedup 1.0000x reference)
#include <cuda_runtime.h>
#include <cstdint>

#define B 8
#define C 128
#define H 256
#define W 256
#define HW (H*W)        // 65536
#define HW4 (HW/4)      // 16384

// scratch: pooled max map [B, H, W] (attn is computed in-register, never stored)
__device__ float g_pooled[B * HW];

// ---------------------------------------------------------------------------
// Fused pipeline step kernel.
//   blocks [0, nMul)        : convMul role for batch b_mul
//       512 blocks = 64 spatial tiles (64x16) x 8 channel-groups (16 ch).
//       Each block: load pooled halo (from L2), conv7x7+sigmoid for its tile
//       (redundant across the 8 groups - trivial), then 16 channels of
//       out = x * attn with streaming cache hints.
//   blocks [nMul, nMul+256) : pool role for batch b_pool
//       256 blocks = 64 float4-pixels x 4 channel-groups, smem max-reduce.
//       Normal cache policy -> x_{b_pool} left resident in L2 for next step.
// ---------------------------------------------------------------------------
__global__ void __launch_bounds__(256) step_kernel(
        const float* __restrict__ x, float* __restrict__ out,
        const float* __restrict__ cw, const float* __restrict__ cb,
        int b_pool, int b_mul, int nMul)
{
    if ((int)blockIdx.x < nMul) {
        // ---------------- convMul role ----------------
        const int rid = blockIdx.x;
        const int t   = rid >> 3;          // tile 0..63
        const int chg = rid & 7;           // channel group 0..7 (16 ch each)
        const int tx0 = (t & 3) * 64;      // 4 tiles across
        const int ty0 = (t >> 2) * 16;     // 16 tiles down

        __shared__ float s[22][72];        // 70 used, +2 pad
        const float* pb = g_pooled + b_mul * HW;
        for (int i = threadIdx.x; i < 22 * 70; i += 256) {
            int ly = i / 70;
            int lx = i - ly * 70;
            int gy = ty0 + ly - 3;
            int gx = tx0 + lx - 3;
            float v = 0.0f;
            if (gy >= 0 && gy < H && gx >= 0 && gx < W) v = pb[gy * W + gx];
            s[ly][lx] = v;
        }
        __syncthreads();

        float wr[49];
        #pragma unroll
        for (int i = 0; i < 49; ++i) wr[i] = __ldg(&cw[i]);
        const float bias = __ldg(&cb[0]);

        const int lx4 = threadIdx.x & 15;  // float4 column 0..15
        const int ly  = threadIdx.x >> 4;  // row 0..15

        float a4[4];
        #pragma unroll
        for (int j = 0; j < 4; ++j) {
            float acc = bias;
            #pragma unroll
            for (int i = 0; i < 7; ++i)
                #pragma unroll
                for (int k = 0; k < 7; ++k)
                    acc = fmaf(s[ly + i][lx4 * 4 + j + k], wr[i * 7 + k], acc);
            a4[j] = 1.0f / (1.0f + __expf(-acc));
        }

        const int hw4 = (ty0 + ly) * (W / 4) + (tx0 >> 2) + lx4;
        const float4* xp = reinterpret_cast<const float4*>(x)
                           + ((size_t)b_mul * C + chg * 16) * HW4 + hw4;
        float4* op = reinterpret_cast<float4*>(out)
                     + ((size_t)b_mul * C + chg * 16) * HW4 + hw4;

        #pragma unroll 4
        for (int c = 0; c < 16; ++c) {
            float4 v = __ldcs(xp + (size_t)c * HW4);   // last use: evict-first
            v.x *= a4[0]; v.y *= a4[1]; v.z *= a4[2]; v.w *= a4[3];
            __stcs(op + (size_t)c * HW4, v);            // streaming store
        }
    } else {
        // ---------------- pool role ----------------
        const int rid = blockIdx.x - nMul;
        __shared__ float4 red[256];
        const int tid = threadIdx.x;
        const int grp = tid >> 6;          // 0..3 channel group (32 ch)
        const int pix = tid & 63;          // 0..63 float4 pixel
        const int hw4 = rid * 64 + pix;

        const float4* p = reinterpret_cast<const float4*>(x)
                          + ((size_t)b_pool * C + (size_t)grp * 32) * HW4 + hw4;

        float4 m = p[0];
        #pragma unroll 8
        for (int c = 1; c < 32; ++c) {
            float4 v = p[(size_t)c * HW4];
            m.x = fmaxf(m.x, v.x);
            m.y = fmaxf(m.y, v.y);
            m.z = fmaxf(m.z, v.z);
            m.w = fmaxf(m.w, v.w);
        }
        red[tid] = m;
        __syncthreads();

        if (grp == 0) {
            float4 a  = red[pix];
            float4 b1 = red[64 + pix];
            float4 c1 = red[128 + pix];
            float4 d1 = red[192 + pix];
            a.x = fmaxf(fmaxf(a.x, b1.x), fmaxf(c1.x, d1.x));
            a.y = fmaxf(fmaxf(a.y, b1.y), fmaxf(c1.y, d1.y));
            a.z = fmaxf(fmaxf(a.z, b1.z), fmaxf(c1.z, d1.z));
            a.w = fmaxf(fmaxf(a.w, b1.w), fmaxf(c1.w, d1.w));
            reinterpret_cast<float4*>(g_pooled)[(size_t)b_pool * HW4 + hw4] = a;
        }
    }
}

// ---------------------------------------------------------------------------
extern "C" void kernel_launch(void* const* d_in, const int* in_sizes, int n_in,
                              void* d_out, int out_size) {
    const float* x  = (const float*)d_in[0];
    const float* cw = (const float*)d_in[1];   // [1,1,7,7]
    const float* cb = (const float*)d_in[2];   // [1]
    float* out = (float*)d_out;

    // Pipeline: step s runs pool(s) and convMul(s-1) concurrently in one grid.
    for (int s = 0; s <= B; ++s) {
        int b_pool = (s < B) ? s : -1;
        int b_mul  = s - 1;                       // -1 on first step
        int nMul   = (b_mul >= 0) ? 512 : 0;
        int nPool  = (b_pool >= 0) ? 256 : 0;
        step_kernel<<<nMul + nPool, 256>>>(x, out, cw, cb, b_pool, b_mul, nMul);
    }
}

// round 4
// speedup vs baseline: 1.3137x; 1.3137x over previous
#include <cuda_runtime.h>
#include <cstdint>

#define B 8
#define C 128
#define H 256
#define W 256
#define HW (H*W)        // 65536
#define HW4 (HW/4)      // 16384

#define POOL_UNITS 256          // per batch: 64 float4-pixels x 4 ch-groups
#define MUL_UNITS  512          // per batch: 64 spatial tiles x 8 ch-groups
#define STEP_T     (POOL_UNITS + MUL_UNITS)              // 768
#define TOTAL_T    (POOL_UNITS + 7 * STEP_T + MUL_UNITS) // 6144

__device__ float g_pooled[B * HW];
__device__ int   g_ticket;
__device__ int   g_pool_done[B];

__global__ void reset_kernel() {
    g_ticket = 0;
    #pragma unroll
    for (int i = 0; i < B; ++i) g_pool_done[i] = 0;
}

// ---------------------------------------------------------------------------
// Persistent pipelined kernel. Work units via global ticket queue:
//   tickets [0,256)        : pool batch 0
//   steps s=1..7 (768 ea)  : interleaved  pool(s) (l%3==0) / mul(s-1)
//   last 512               : mul batch 7
// ---------------------------------------------------------------------------
__global__ void __launch_bounds__(256, 4) pipeline_kernel(
        const float* __restrict__ x, float* __restrict__ out,
        const float* __restrict__ cw, const float* __restrict__ cb)
{
    __shared__ float  s[22][72];     // conv halo tile (70 cols used)
    __shared__ float4 red[256];      // pool reduce
    __shared__ float  sw[50];        // 49 weights + bias
    __shared__ int    s_ticket;

    const int tid = threadIdx.x;
    if (tid < 49) sw[tid] = cw[tid];
    if (tid == 49) sw[49] = cb[0];

    for (;;) {
        if (tid == 0) s_ticket = atomicAdd(&g_ticket, 1);
        __syncthreads();
        const int t = s_ticket;
        if (t >= TOTAL_T) break;

        int b, u;
        bool is_pool;
        if (t < POOL_UNITS) {
            is_pool = true; b = 0; u = t;
        } else if (t < POOL_UNITS + 7 * STEP_T) {
            int r = t - POOL_UNITS;
            int st = r / STEP_T;          // 0..6
            int l  = r % STEP_T;          // 0..767
            int q  = l / 3;               // 0..255
            int m  = l - q * 3;
            if (m == 0) { is_pool = true;  b = st + 1; u = q; }
            else        { is_pool = false; b = st;     u = 2 * q + (m - 1); }
        } else {
            is_pool = false; b = 7; u = t - (POOL_UNITS + 7 * STEP_T);
        }

        if (is_pool) {
            // ---- pool unit: 64 float4 pixels, 4 channel groups of 32 ----
            const int grp = tid >> 6;
            const int pix = tid & 63;
            const int hw4 = u * 64 + pix;
            const float4* p = reinterpret_cast<const float4*>(x)
                              + ((size_t)b * C + (size_t)grp * 32) * HW4 + hw4;
            float4 m4 = p[0];
            #pragma unroll 8
            for (int c = 1; c < 32; ++c) {
                float4 v = p[(size_t)c * HW4];
                m4.x = fmaxf(m4.x, v.x);
                m4.y = fmaxf(m4.y, v.y);
                m4.z = fmaxf(m4.z, v.z);
                m4.w = fmaxf(m4.w, v.w);
            }
            red[tid] = m4;
            __syncthreads();
            if (grp == 0) {
                float4 a  = red[pix];
                float4 b1 = red[64 + pix];
                float4 c1 = red[128 + pix];
                float4 d1 = red[192 + pix];
                a.x = fmaxf(fmaxf(a.x, b1.x), fmaxf(c1.x, d1.x));
                a.y = fmaxf(fmaxf(a.y, b1.y), fmaxf(c1.y, d1.y));
                a.z = fmaxf(fmaxf(a.z, b1.z), fmaxf(c1.z, d1.z));
                a.w = fmaxf(fmaxf(a.w, b1.w), fmaxf(c1.w, d1.w));
                reinterpret_cast<float4*>(g_pooled)[(size_t)b * HW4 + hw4] = a;
            }
            __syncthreads();
            if (tid == 0) {
                __threadfence();
                atomicAdd(&g_pool_done[b], 1);
            }
        } else {
            // ---- conv+mul unit: spatial tile 64x16, 16 channels ----
            const int tile = u >> 3;
            const int chg  = u & 7;
            const int tx0  = (tile & 3) * 64;
            const int ty0  = (tile >> 2) * 16;

            if (tid == 0) {
                while (*(volatile int*)&g_pool_done[b] < POOL_UNITS)
                    __nanosleep(100);
                __threadfence();
            }
            __syncthreads();

            const float* pb = g_pooled + b * HW;
            for (int i = tid; i < 22 * 70; i += 256) {
                int ly = i / 70;
                int lx = i - ly * 70;
                int gy = ty0 + ly - 3;
                int gx = tx0 + lx - 3;
                float v = 0.0f;
                if (gy >= 0 && gy < H && gx >= 0 && gx < W) v = pb[gy * W + gx];
                s[ly][lx] = v;
            }
            __syncthreads();

            const int lx4 = tid & 15;   // float4 column within tile
            const int ly  = tid >> 4;   // row 0..15

            float a4[4];
            #pragma unroll
            for (int j = 0; j < 4; ++j) {
                float acc = sw[49];
                #pragma unroll
                for (int i = 0; i < 7; ++i)
                    #pragma unroll
                    for (int k = 0; k < 7; ++k)
                        acc = fmaf(s[ly + i][lx4 * 4 + j + k], sw[i * 7 + k], acc);
                a4[j] = 1.0f / (1.0f + __expf(-acc));
            }

            const int hw4 = (ty0 + ly) * (W / 4) + (tx0 >> 2) + lx4;
            const float4* xp = reinterpret_cast<const float4*>(x)
                               + ((size_t)b * C + chg * 16) * HW4 + hw4;
            float4* op = reinterpret_cast<float4*>(out)
                         + ((size_t)b * C + chg * 16) * HW4 + hw4;

            #pragma unroll 4
            for (int c = 0; c < 16; ++c) {
                float4 v = __ldcs(xp + (size_t)c * HW4);   // L2 hit, evict-first
                v.x *= a4[0]; v.y *= a4[1]; v.z *= a4[2]; v.w *= a4[3];
                __stcs(op + (size_t)c * HW4, v);            // streaming store
            }
        }
        __syncthreads();
    }
}

// ---------------------------------------------------------------------------
extern "C" void kernel_launch(void* const* d_in, const int* in_sizes, int n_in,
                              void* d_out, int out_size) {
    const float* x  = (const float*)d_in[0];
    const float* cw = (const float*)d_in[1];
    const float* cb = (const float*)d_in[2];
    float* out = (float*)d_out;

    reset_kernel<<<1, 1>>>();
    // 592 blocks = 148 SMs x occ 4 (launch_bounds(256,4) caps regs at 64).
    // Ticket queue makes any grid size deadlock-free (work is pulled, not
    // pre-assigned; issued tickets are always held by running blocks).
    pipeline_kernel<<<592, 256>>>(x, out, cw, cb);
}

// round 5
// speedup vs baseline: 1.3590x; 1.0345x over previous
#include <cuda_runtime.h>
#include <cstdint>

#define B 8
#define C 128
#define H 256
#define W 256
#define HW (H*W)        // 65536
#define HW4 (HW/4)      // 16384

#define POOL_UNITS 256   // per batch
#define CONV_UNITS 64    // per batch (64x16 tile each)
#define MUL_UNITS  512   // per batch (64 tiles x 8 ch-groups of 16)
#define STEP_T     (CONV_UNITS + 2*POOL_UNITS + MUL_UNITS - POOL_UNITS) // 64+512+256=832
#define TOTAL_T    (POOL_UNITS + 7 * 832 + (CONV_UNITS + MUL_UNITS))    // 256+5824+576=6656

__device__ float g_pooled[B * HW];
__device__ float g_attn[B * HW];
__device__ int   g_ticket;
__device__ int   g_pool_done[B];
__device__ int   g_conv_done[B];

__global__ void reset_kernel() {
    g_ticket = 0;
    #pragma unroll
    for (int i = 0; i < B; ++i) { g_pool_done[i] = 0; g_conv_done[i] = 0; }
}

// ---------------------------------------------------------------------------
// Persistent 3-role pipeline. Ticket order:
//   [pool(0) x256]
//   step s=1..7: [conv(s-1) x64][ (mul(s-1),mul(s-1),pool(s)) x256 ]
//   tail:        [conv(7) x64][ mul(7) x512 ]
// Dependencies: conv(b) waits pool_done[b]==256; mul(b) waits conv_done[b]==64.
// Tickets are issued in dependency order -> pull-model is deadlock-free.
// ---------------------------------------------------------------------------
__global__ void __launch_bounds__(256, 5) pipeline_kernel(
        const float* __restrict__ x, float* __restrict__ out,
        const float* __restrict__ cw, const float* __restrict__ cb)
{
    __shared__ float  s[22][72];
    __shared__ float4 red[256];
    __shared__ float  sw[50];
    __shared__ int    s_ticket;

    const int tid = threadIdx.x;
    if (tid < 49) sw[tid] = cw[tid];
    if (tid == 49) sw[49] = cb[0];

    for (;;) {
        if (tid == 0) s_ticket = atomicAdd(&g_ticket, 1);
        __syncthreads();
        const int t = s_ticket;
        if (t >= TOTAL_T) break;

        int role, b, u;           // role: 0=pool 1=conv 2=mul
        if (t < POOL_UNITS) {
            role = 0; b = 0; u = t;
        } else if (t < POOL_UNITS + 7 * 832) {
            int r  = t - POOL_UNITS;
            int st = r / 832;               // 0..6
            int l  = r - st * 832;
            if (l < CONV_UNITS) { role = 1; b = st; u = l; }
            else {
                int l2 = l - CONV_UNITS;
                int q  = l2 / 3;
                int m  = l2 - q * 3;
                if (m < 2) { role = 2; b = st;     u = 2 * q + m; }
                else       { role = 0; b = st + 1; u = q; }
            }
        } else {
            int l = t - (POOL_UNITS + 7 * 832);
            if (l < CONV_UNITS) { role = 1; b = 7; u = l; }
            else                { role = 2; b = 7; u = l - CONV_UNITS; }
        }

        if (role == 0) {
            // ---- pool: 64 float4 pixels x 4 channel-groups of 32 ----
            const int grp = tid >> 6;
            const int pix = tid & 63;
            const int hw4 = u * 64 + pix;
            const float4* p = reinterpret_cast<const float4*>(x)
                              + ((size_t)b * C + (size_t)grp * 32) * HW4 + hw4;
            float4 m4 = p[0];
            #pragma unroll 8
            for (int c = 1; c < 32; ++c) {
                float4 v = p[(size_t)c * HW4];
                m4.x = fmaxf(m4.x, v.x);
                m4.y = fmaxf(m4.y, v.y);
                m4.z = fmaxf(m4.z, v.z);
                m4.w = fmaxf(m4.w, v.w);
            }
            red[tid] = m4;
            __syncthreads();
            if (grp == 0) {
                float4 a  = red[pix];
                float4 b1 = red[64 + pix];
                float4 c1 = red[128 + pix];
                float4 d1 = red[192 + pix];
                a.x = fmaxf(fmaxf(a.x, b1.x), fmaxf(c1.x, d1.x));
                a.y = fmaxf(fmaxf(a.y, b1.y), fmaxf(c1.y, d1.y));
                a.z = fmaxf(fmaxf(a.z, b1.z), fmaxf(c1.z, d1.z));
                a.w = fmaxf(fmaxf(a.w, b1.w), fmaxf(c1.w, d1.w));
                reinterpret_cast<float4*>(g_pooled)[(size_t)b * HW4 + hw4] = a;
            }
            __syncthreads();
            if (tid == 0) { __threadfence(); atomicAdd(&g_pool_done[b], 1); }
        } else if (role == 1) {
            // ---- conv+sigmoid: one 64x16 tile -> g_attn ----
            const int tx0 = (u & 3) * 64;
            const int ty0 = (u >> 2) * 16;

            if (tid == 0) {
                while (*(volatile int*)&g_pool_done[b] < POOL_UNITS)
                    __nanosleep(64);
                __threadfence();
            }
            __syncthreads();

            const float* pb = g_pooled + b * HW;
            for (int i = tid; i < 22 * 70; i += 256) {
                int ly = i / 70;
                int lx = i - ly * 70;
                int gy = ty0 + ly - 3;
                int gx = tx0 + lx - 3;
                float v = 0.0f;
                if (gy >= 0 && gy < H && gx >= 0 && gx < W) v = pb[gy * W + gx];
                s[ly][lx] = v;
            }
            __syncthreads();

            const int lx4 = tid & 15;
            const int ly  = tid >> 4;
            float4 a4;
            float* ap = &a4.x;
            #pragma unroll
            for (int j = 0; j < 4; ++j) {
                float acc = sw[49];
                #pragma unroll
                for (int i = 0; i < 7; ++i)
                    #pragma unroll
                    for (int k = 0; k < 7; ++k)
                        acc = fmaf(s[ly + i][lx4 * 4 + j + k], sw[i * 7 + k], acc);
                ap[j] = 1.0f / (1.0f + __expf(-acc));
            }
            const int hw4 = (ty0 + ly) * (W / 4) + (tx0 >> 2) + lx4;
            reinterpret_cast<float4*>(g_attn)[(size_t)b * HW4 + hw4] = a4;
            __syncthreads();
            if (tid == 0) { __threadfence(); atomicAdd(&g_conv_done[b], 1); }
        } else {
            // ---- mul: pure streaming, 16 channels, MLP-8 batches ----
            const int tile = u >> 3;
            const int chg  = u & 7;
            const int tx0  = (tile & 3) * 64;
            const int ty0  = (tile >> 2) * 16;

            if (tid == 0) {
                while (*(volatile int*)&g_conv_done[b] < CONV_UNITS)
                    __nanosleep(64);
                __threadfence();
            }
            __syncthreads();

            const int lx4 = tid & 15;
            const int ly  = tid >> 4;
            const int hw4 = (ty0 + ly) * (W / 4) + (tx0 >> 2) + lx4;

            const float4 a = __ldg(reinterpret_cast<const float4*>(g_attn)
                                   + (size_t)b * HW4 + hw4);
            const float4* xp = reinterpret_cast<const float4*>(x)
                               + ((size_t)b * C + chg * 16) * HW4 + hw4;
            float4* op = reinterpret_cast<float4*>(out)
                         + ((size_t)b * C + chg * 16) * HW4 + hw4;

            #pragma unroll
            for (int h = 0; h < 2; ++h) {
                float4 v[8];
                #pragma unroll
                for (int j = 0; j < 8; ++j)
                    v[j] = __ldcs(xp + (size_t)(h * 8 + j) * HW4);
                #pragma unroll
                for (int j = 0; j < 8; ++j) {
                    v[j].x *= a.x; v[j].y *= a.y; v[j].z *= a.z; v[j].w *= a.w;
                    __stcs(op + (size_t)(h * 8 + j) * HW4, v[j]);
                }
            }
        }
        __syncthreads();
    }
}

// ---------------------------------------------------------------------------
extern "C" void kernel_launch(void* const* d_in, const int* in_sizes, int n_in,
                              void* d_out, int out_size) {
    const float* x  = (const float*)d_in[0];
    const float* cw = (const float*)d_in[1];
    const float* cb = (const float*)d_in[2];
    float* out = (float*)d_out;

    reset_kernel<<<1, 1>>>();
    pipeline_kernel<<<740, 256>>>(x, out, cw, cb);   // 148 SMs x 5
}

// round 6
// speedup vs baseline: 1.3746x; 1.0115x over previous
#include <cuda_runtime.h>
#include <cstdint>

#define B 8
#define C 128
#define H 256
#define W 256
#define HW (H*W)        // 65536
#define HW4 (HW/4)      // 16384

#define POOL_UNITS 256   // per batch
#define CONV_UNITS 64    // per batch (64x16 tile each)
#define MUL_UNITS  512   // per batch (64 tiles x 8 ch-groups of 16)
#define STEP_T     832                                   // 64 conv + 512 mul + 256 pool
#define TOTAL_T    (POOL_UNITS + 7 * STEP_T + (CONV_UNITS + MUL_UNITS))  // 6656

__device__ float g_pooled[B * HW];
__device__ float g_attn[B * HW];
__device__ int   g_ticket;
__device__ int   g_pool_done[B];
__device__ int   g_conv_done[B];

__global__ void reset_kernel() {
    g_ticket = 0;
    #pragma unroll
    for (int i = 0; i < B; ++i) { g_pool_done[i] = 0; g_conv_done[i] = 0; }
}

// ---------------------------------------------------------------------------
// Persistent 3-role pipeline (tickets in dependency order -> deadlock-free).
//   [pool(0) x256]
//   step s=1..7: [conv(s-1) x64][ (mul(s-1),mul(s-1),pool(s)) x256 ]
//   tail:        [conv(7) x64][ mul(7) x512 ]
// ---------------------------------------------------------------------------
__global__ void __launch_bounds__(256, 4) pipeline_kernel(
        const float* __restrict__ x, float* __restrict__ out,
        const float* __restrict__ cw, const float* __restrict__ cb)
{
    __shared__ float  s[22][72];
    __shared__ float4 red[256];
    __shared__ float  sw[50];
    __shared__ int    s_ticket;

    const int tid = threadIdx.x;
    if (tid < 49) sw[tid] = cw[tid];
    if (tid == 49) sw[49] = cb[0];

    for (;;) {
        if (tid == 0) s_ticket = atomicAdd(&g_ticket, 1);
        __syncthreads();
        const int t = s_ticket;
        if (t >= TOTAL_T) break;

        int role, b, u;           // role: 0=pool 1=conv 2=mul
        if (t < POOL_UNITS) {
            role = 0; b = 0; u = t;
        } else if (t < POOL_UNITS + 7 * STEP_T) {
            int r  = t - POOL_UNITS;
            int st = r / STEP_T;            // 0..6
            int l  = r - st * STEP_T;
            if (l < CONV_UNITS) { role = 1; b = st; u = l; }
            else {
                int l2 = l - CONV_UNITS;
                int q  = l2 / 3;
                int m  = l2 - q * 3;
                if (m < 2) { role = 2; b = st;     u = 2 * q + m; }
                else       { role = 0; b = st + 1; u = q; }
            }
        } else {
            int l = t - (POOL_UNITS + 7 * STEP_T);
            if (l < CONV_UNITS) { role = 1; b = 7; u = l; }
            else                { role = 2; b = 7; u = l - CONV_UNITS; }
        }

        if (role == 0) {
            // ---- pool: 64 float4 pixels x 4 ch-groups of 32, MLP=8 ----
            const int grp = tid >> 6;
            const int pix = tid & 63;
            const int hw4 = u * 64 + pix;
            const float4* p = reinterpret_cast<const float4*>(x)
                              + ((size_t)b * C + (size_t)grp * 32) * HW4 + hw4;
            float4 m4 = make_float4(-3.4e38f, -3.4e38f, -3.4e38f, -3.4e38f);
            #pragma unroll
            for (int g = 0; g < 4; ++g) {
                float4 buf[8];
                #pragma unroll
                for (int j = 0; j < 8; ++j)
                    buf[j] = p[(size_t)(g * 8 + j) * HW4];   // 8 LDGs in flight
                #pragma unroll
                for (int j = 0; j < 8; ++j) {
                    m4.x = fmaxf(m4.x, buf[j].x);
                    m4.y = fmaxf(m4.y, buf[j].y);
                    m4.z = fmaxf(m4.z, buf[j].z);
                    m4.w = fmaxf(m4.w, buf[j].w);
                }
            }
            red[tid] = m4;
            __syncthreads();
            if (grp == 0) {
                float4 a  = red[pix];
                float4 b1 = red[64 + pix];
                float4 c1 = red[128 + pix];
                float4 d1 = red[192 + pix];
                a.x = fmaxf(fmaxf(a.x, b1.x), fmaxf(c1.x, d1.x));
                a.y = fmaxf(fmaxf(a.y, b1.y), fmaxf(c1.y, d1.y));
                a.z = fmaxf(fmaxf(a.z, b1.z), fmaxf(c1.z, d1.z));
                a.w = fmaxf(fmaxf(a.w, b1.w), fmaxf(c1.w, d1.w));
                reinterpret_cast<float4*>(g_pooled)[(size_t)b * HW4 + hw4] = a;
            }
            __syncthreads();
            if (tid == 0) { __threadfence(); atomicAdd(&g_pool_done[b], 1); }
        } else if (role == 1) {
            // ---- conv+sigmoid: one 64x16 tile -> g_attn ----
            const int tx0 = (u & 3) * 64;
            const int ty0 = (u >> 2) * 16;

            if (tid == 0) {
                while (*(volatile int*)&g_pool_done[b] < POOL_UNITS)
                    __nanosleep(64);
                __threadfence();
            }
            __syncthreads();

            const float* pb = g_pooled + b * HW;
            for (int i = tid; i < 22 * 70; i += 256) {
                int ly = i / 70;
                int lx = i - ly * 70;
                int gy = ty0 + ly - 3;
                int gx = tx0 + lx - 3;
                float v = 0.0f;
                if (gy >= 0 && gy < H && gx >= 0 && gx < W) v = pb[gy * W + gx];
                s[ly][lx] = v;
            }
            __syncthreads();

            const int lx4 = tid & 15;
            const int ly  = tid >> 4;
            float4 a4;
            float* ap = &a4.x;
            #pragma unroll
            for (int j = 0; j < 4; ++j) {
                float acc = sw[49];
                #pragma unroll
                for (int i = 0; i < 7; ++i)
                    #pragma unroll
                    for (int k = 0; k < 7; ++k)
                        acc = fmaf(s[ly + i][lx4 * 4 + j + k], sw[i * 7 + k], acc);
                ap[j] = 1.0f / (1.0f + __expf(-acc));
            }
            const int hw4 = (ty0 + ly) * (W / 4) + (tx0 >> 2) + lx4;
            reinterpret_cast<float4*>(g_attn)[(size_t)b * HW4 + hw4] = a4;
            __syncthreads();
            if (tid == 0) { __threadfence(); atomicAdd(&g_conv_done[b], 1); }
        } else {
            // ---- mul: pure streaming, 16 channels, MLP-8 batches ----
            const int tile = u >> 3;
            const int chg  = u & 7;
            const int tx0  = (tile & 3) * 64;
            const int ty0  = (tile >> 2) * 16;

            if (tid == 0) {
                while (*(volatile int*)&g_conv_done[b] < CONV_UNITS)
                    __nanosleep(64);
                __threadfence();
            }
            __syncthreads();

            const int lx4 = tid & 15;
            const int ly  = tid >> 4;
            const int hw4 = (ty0 + ly) * (W / 4) + (tx0 >> 2) + lx4;

            const float4 a = __ldg(reinterpret_cast<const float4*>(g_attn)
                                   + (size_t)b * HW4 + hw4);
            const float4* xp = reinterpret_cast<const float4*>(x)
                               + ((size_t)b * C + chg * 16) * HW4 + hw4;
            float4* op = reinterpret_cast<float4*>(out)
                         + ((size_t)b * C + chg * 16) * HW4 + hw4;

            #pragma unroll
            for (int h = 0; h < 2; ++h) {
                float4 v[8];
                #pragma unroll
                for (int j = 0; j < 8; ++j)
                    v[j] = __ldcs(xp + (size_t)(h * 8 + j) * HW4);
                #pragma unroll
                for (int j = 0; j < 8; ++j) {
                    v[j].x *= a.x; v[j].y *= a.y; v[j].z *= a.z; v[j].w *= a.w;
                    __stcs(op + (size_t)(h * 8 + j) * HW4, v[j]);
                }
            }
        }
        __syncthreads();
    }
}

// ---------------------------------------------------------------------------
extern "C" void kernel_launch(void* const* d_in, const int* in_sizes, int n_in,
                              void* d_out, int out_size) {
    const float* x  = (const float*)d_in[0];
    const float* cw = (const float*)d_in[1];
    const float* cb = (const float*)d_in[2];
    float* out = (float*)d_out;

    reset_kernel<<<1, 1>>>();
    pipeline_kernel<<<592, 256>>>(x, out, cw, cb);   // 148 SMs x 4
}